// round 1
// baseline (speedup 1.0000x reference)
#include <cuda_runtime.h>

// Problem constants (fixed shapes from reference):
//   dct: [16, 64, 256, 256] fp32, mean/std: [64] fp32
//   out: [16, 1, 2048, 2048] fp32
#define HW      65536        // 256*256
#define OUTW    2048

__global__ __launch_bounds__(256) void idct_kernel(
    const float* __restrict__ dct,
    const float* __restrict__ mean_,
    const float* __restrict__ std_,
    float* __restrict__ out)
{
    // s_hx[u][x] = 0.5*c_u*cos((2x+1)u*pi/16)
    // s_hy[v][y] = s_hx[v][y] / 255   (only y=0..3 needed due to symmetry)
    __shared__ float s_hx[8][8];
    __shared__ float s_hy[8][4];
    __shared__ float s_std[64];
    __shared__ float s_mean[64];

    int tid = threadIdx.x;
    if (tid < 64) {
        int u = tid >> 3, x = tid & 7;
        float c = (u == 0) ? 0.70710678118654752440f : 1.0f;
        float h = cospif((float)((2 * x + 1) * u) * (1.0f / 16.0f));
        float v = 0.5f * c * h;
        s_hx[u][x] = v;
        if (x < 4) s_hy[u][x] = v * (1.0f / 255.0f);
        s_std[tid]  = std_[tid];
        s_mean[tid] = mean_[tid];
    }
    __syncthreads();

    unsigned gid = blockIdx.x * 256u + (unsigned)tid;   // 0 .. 16*65536-1
    unsigned b   = gid >> 16;
    unsigned pos = gid & 65535u;                         // h*256 + w
    const float* src = dct + (size_t)b * 64u * HW + pos;

    // acc[x][y]   = E[x][y] + O[x][y]      for x in 0..3
    // acc[7-x][y] = E[x][y] - O[x][y]
    // K = 128/255 folded into E init (appears with + sign in both rows).
    const float K = 128.0f / 255.0f;
    float E[4][8], O[4][8];
    #pragma unroll
    for (int xp = 0; xp < 4; xp++)
        #pragma unroll
        for (int y = 0; y < 8; y++) { E[xp][y] = K; O[xp][y] = 0.0f; }

    #pragma unroll
    for (int u = 0; u < 8; u++) {
        // 8 coalesced channel loads (stride 256KB between channels)
        float d[8];
        #pragma unroll
        for (int v = 0; v < 8; v++) {
            int c = u * 8 + v;
            d[v] = fmaf(__ldg(src + (size_t)c * HW), s_std[c], s_mean[c]);
        }

        // y-pass with even/odd v butterfly: t[y]=te+to, t[7-y]=te-to
        float te[4] = {0.f,0.f,0.f,0.f}, to[4] = {0.f,0.f,0.f,0.f};
        #pragma unroll
        for (int vp = 0; vp < 4; vp++) {
            #pragma unroll
            for (int yp = 0; yp < 4; yp++) {
                te[yp] = fmaf(s_hy[2*vp    ][yp], d[2*vp    ], te[yp]);
                to[yp] = fmaf(s_hy[2*vp + 1][yp], d[2*vp + 1], to[yp]);
            }
        }
        float t[8];
        #pragma unroll
        for (int yp = 0; yp < 4; yp++) {
            t[yp]     = te[yp] + to[yp];
            t[7 - yp] = te[yp] - to[yp];
        }

        // x-pass accumulation: even u -> E, odd u -> O (compile-time branch)
        #pragma unroll
        for (int xp = 0; xp < 4; xp++) {
            float w = s_hx[u][xp];
            if ((u & 1) == 0) {
                #pragma unroll
                for (int y = 0; y < 8; y++) E[xp][y] = fmaf(w, t[y], E[xp][y]);
            } else {
                #pragma unroll
                for (int y = 0; y < 8; y++) O[xp][y] = fmaf(w, t[y], O[xp][y]);
            }
        }
    }

    // Write 8x8 pixel block: out[b, 8h+x, 8w+y], two STG.128 per row.
    unsigned hh = pos >> 8, ww = pos & 255u;
    float* dst = out + (size_t)b * ((size_t)OUTW * OUTW)
                     + (size_t)hh * 8 * OUTW + (size_t)ww * 8;

    #pragma unroll
    for (int xp = 0; xp < 4; xp++) {
        float4 a, bq;
        a.x  = E[xp][0] + O[xp][0];  a.y  = E[xp][1] + O[xp][1];
        a.z  = E[xp][2] + O[xp][2];  a.w  = E[xp][3] + O[xp][3];
        bq.x = E[xp][4] + O[xp][4];  bq.y = E[xp][5] + O[xp][5];
        bq.z = E[xp][6] + O[xp][6];  bq.w = E[xp][7] + O[xp][7];
        *(float4*)(dst + (size_t)xp * OUTW)     = a;
        *(float4*)(dst + (size_t)xp * OUTW + 4) = bq;

        float4 c4, d4;
        c4.x = E[xp][0] - O[xp][0];  c4.y = E[xp][1] - O[xp][1];
        c4.z = E[xp][2] - O[xp][2];  c4.w = E[xp][3] - O[xp][3];
        d4.x = E[xp][4] - O[xp][4];  d4.y = E[xp][5] - O[xp][5];
        d4.z = E[xp][6] - O[xp][6];  d4.w = E[xp][7] - O[xp][7];
        *(float4*)(dst + (size_t)(7 - xp) * OUTW)     = c4;
        *(float4*)(dst + (size_t)(7 - xp) * OUTW + 4) = d4;
    }
}

extern "C" void kernel_launch(void* const* d_in, const int* in_sizes, int n_in,
                              void* d_out, int out_size)
{
    (void)in_sizes; (void)n_in; (void)out_size;
    const float* dct   = (const float*)d_in[0];
    const float* mean_ = (const float*)d_in[1];
    const float* std_  = (const float*)d_in[2];
    float* out = (float*)d_out;
    // 16*256*256 = 1,048,576 blocks of 8x8 pixels, 1 thread each.
    idct_kernel<<<4096, 256>>>(dct, mean_, std_, out);
}